// round 15
// baseline (speedup 1.0000x reference)
#include <cuda_runtime.h>
#include <cuda_fp16.h>
#include <cstdint>
#include <math.h>

// Problem constants
#define NB 16
#define NC 64
#define NO 64
#define NH 160
#define NW 160
#define NK 8
#define NA 16
#define KHW 9
#define PLANE (NH*NW)          // 25600
#define NCH 4                  // channel chunks of 16
// Packed 16B-unit smem layouts (no padding, conflict-free by unit addressing)
#define XS_WORDS_BUF (3*2*162*4)   // 3888 u32: [kh][kq][col] units
#define WS_WORDS_BUF (KHW*2*NO*4)  // 4608 u32: [tap][kq][o] units
#define SMEM_BYTES ((2*XS_WORDS_BUF + 2*WS_WORDS_BUF) * 4)   // 67968
// epilogue staging: 64 o x 172-padded floats = 44032 B (reuses dsm)

// Scratch (device globals; no allocation allowed)
__device__ float    g_rows[NB*NH*NC];          // per-(b,row) channel sums
__device__ float    g_chan[NB*NC];
__device__ float    g_filt[NB*NO];
__device__ float    g_spat[NB*KHW];
__device__ float    g_katt[NB*NK];
__device__ uint32_t g_Wh  [NB*NCH*WS_WORDS_BUF];        // pre-packed B image
__device__ uint32_t g_xh  [(size_t)NB*NH*NW*32];        // x as half2, channel-last

// ---------------------------------------------------------------------------
__device__ __forceinline__ uint32_t smem_u32(const void* p) {
    uint32_t a;
    asm("{ .reg .u64 t; cvta.to.shared.u64 t, %1; cvt.u32.u64 %0, t; }" : "=r"(a) : "l"(p));
    return a;
}
__device__ __forceinline__ void mma16(float* d, const uint32_t* a, const uint32_t* b) {
    asm volatile(
        "mma.sync.aligned.m16n8k16.row.col.f32.f16.f16.f32 "
        "{%0,%1,%2,%3}, {%4,%5,%6,%7}, {%8,%9}, {%0,%1,%2,%3};"
        : "+f"(d[0]), "+f"(d[1]), "+f"(d[2]), "+f"(d[3])
        : "r"(a[0]), "r"(a[1]), "r"(a[2]), "r"(a[3]), "r"(b[0]), "r"(b[1]));
}
__device__ __forceinline__ void ldsm_x4(uint32_t& r0, uint32_t& r1, uint32_t& r2,
                                        uint32_t& r3, uint32_t addr) {
    asm volatile("ldmatrix.sync.aligned.m8n8.x4.shared.b16 {%0,%1,%2,%3}, [%4];"
                 : "=r"(r0), "=r"(r1), "=r"(r2), "=r"(r3) : "r"(addr));
}
__device__ __forceinline__ void cp16(uint32_t dst, const void* src, bool valid) {
    const int sz = valid ? 16 : 0;
    asm volatile("cp.async.cg.shared.global [%0], [%1], 16, %2;"
                 :: "r"(dst), "l"(src), "r"(sz) : "memory");
}

// ---------------------------------------------------------------------------
// 1) xprep: x [b][c][h][w] fp32 -> g_xh [b][h][w][cp] half2 (channel-last),
//    coalesced writes, per-(b,row) channel sums. 640 threads, div/mod hoisted.
// ---------------------------------------------------------------------------
__global__ __launch_bounds__(640)
void xprep_kernel(const float* __restrict__ x) {
    __shared__ float s[NW * 66];           // 42240 B
    const int row = blockIdx.x;
    const int b   = blockIdx.y;
    const int tid = threadIdx.x;
    const int cb  = tid / NW;              // 0..3
    const int col = tid - cb * NW;         // 0..159

    const float* xr = x + ((size_t)b * NC * NH + row) * NW;
    #pragma unroll
    for (int it = 0; it < 16; it++) {
        const int c = cb + it * 4;
        s[col * 66 + c] = xr[(size_t)c * PLANE + col];
    }
    __syncthreads();

    if (tid < NC) {
        float a = 0.f;
        #pragma unroll 8
        for (int px = 0; px < NW; px++) a += s[px * 66 + tid];
        g_rows[((size_t)b * NH + row) * NC + tid] = a;
    }

    uint32_t* dstrow = g_xh + (((size_t)b * NH + row) * NW) * 32;
    #pragma unroll
    for (int it = 0; it < 8; it++) {
        const int e  = tid + it * 640;     // < 5120
        const int px = e >> 5;
        const int w  = e & 31;
        const float2 v = *(const float2*)&s[px * 66 + 2 * w];
        const __half2 hv = __floats2half2_rn(v.x, v.y);
        dstrow[e] = *(const uint32_t*)&hv;
    }
}

// ---------------------------------------------------------------------------
// 2) Routing MLP + BN + 4 attention heads: one block (128 thr) per batch b.
// ---------------------------------------------------------------------------
__global__ void att_kernel(const float* __restrict__ scale,
                           const float* __restrict__ rw1, const float* __restrict__ rb1,
                           const float* __restrict__ rw2, const float* __restrict__ rb2,
                           const float* __restrict__ fc_w,
                           const float* __restrict__ bn_g, const float* __restrict__ bn_b,
                           const float* __restrict__ bn_m, const float* __restrict__ bn_v,
                           const float* __restrict__ cfc_w, const float* __restrict__ cfc_b,
                           const float* __restrict__ ffc_w, const float* __restrict__ ffc_b,
                           const float* __restrict__ sfc_w, const float* __restrict__ sfc_b,
                           const float* __restrict__ kfc_w, const float* __restrict__ kfc_b) {
    const int b = blockIdx.x;
    const int t = threadIdx.x;
    __shared__ float p[2][64], s[66], h1[128], rt[64], v[16], kl[8];

    {   // GAP: 2 threads per channel, 80 rows each, fixed-order combine
        const int c    = t & 63;
        const int half = t >> 6;
        float a = 0.f;
        #pragma unroll 8
        for (int r = half * 80; r < half * 80 + 80; r++)
            a += g_rows[((size_t)b * NH + r) * NC + c];
        p[half][c] = a;
    }
    __syncthreads();
    if (t < 2) s[t] = 1.f / scale[t];
    if (t >= 2 && t < 66)
        s[t] = (p[0][t - 2] + p[1][t - 2]) * (1.f / (float)PLANE);
    __syncthreads();
    {   // layer 1: [128,66]
        float a = rb1[t];
        #pragma unroll 6
        for (int i = 0; i < 66; i++) a += rw1[t * 66 + i] * s[i];
        h1[t] = fmaxf(a, 0.f);
    }
    __syncthreads();
    if (t < 64) {   // layer 2: [64,128]
        float a = rb2[t];
        #pragma unroll 8
        for (int i = 0; i < 128; i++) a += rw2[t * 128 + i] * h1[i];
        rt[t] = fmaxf(a, 0.f);
    }
    __syncthreads();
    if (t < NA) {   // trunk: fc (no bias) + BN(eval) + relu
        float a = 0.f;
        #pragma unroll 8
        for (int i = 0; i < 64; i++) a += fc_w[t * 64 + i] * rt[i];
        a = (a - bn_m[t]) * rsqrtf(bn_v[t] + 1e-5f) * bn_g[t] + bn_b[t];
        v[t] = fmaxf(a, 0.f);
    }
    __syncthreads();
    if (t < 64) {
        float a = cfc_b[t], f = ffc_b[t];
        #pragma unroll
        for (int i = 0; i < NA; i++) { a += cfc_w[t * NA + i] * v[i]; f += ffc_w[t * NA + i] * v[i]; }
        g_chan[b * NC + t] = 1.f / (1.f + expf(-a));
        g_filt[b * NO + t] = 1.f / (1.f + expf(-f));
    }
    if (t < KHW) {
        float a = sfc_b[t];
        #pragma unroll
        for (int i = 0; i < NA; i++) a += sfc_w[t * NA + i] * v[i];
        g_spat[b * KHW + t] = 1.f / (1.f + expf(-a));
    }
    if (t < NK) {
        float a = kfc_b[t];
        #pragma unroll
        for (int i = 0; i < NA; i++) a += kfc_w[t * NA + i] * v[i];
        kl[t] = a;
    }
    __syncthreads();
    if (t == 0) {   // softmax over 8 experts
        float m = kl[0];
        #pragma unroll
        for (int i = 1; i < NK; i++) m = fmaxf(m, kl[i]);
        float e[NK], sum = 0.f;
        #pragma unroll
        for (int i = 0; i < NK; i++) { e[i] = expf(kl[i] - m); sum += e[i]; }
        float inv = 1.f / sum;
        #pragma unroll
        for (int i = 0; i < NK; i++) g_katt[b * NK + i] = e[i] * inv;
    }
}

// ---------------------------------------------------------------------------
// 3) Aggregated+gated weights -> packed B image: [b][chunk][tap][kq][o] 16B
//    units; unit holds 4 half2 = 8 channels (kq selects channel half of 16).
// ---------------------------------------------------------------------------
__global__ void wprep_kernel(const float* __restrict__ weight) {
    const int b = blockIdx.x >> 6;
    const int o = blockIdx.x & 63;
    __shared__ float ka[NK], sp[KHW], ch[NC], fo;
    const int t = threadIdx.x;
    if (t < NK)                 ka[t]      = g_katt[b * NK + t];
    else if (t < NK + KHW)      sp[t - NK] = g_spat[b * KHW + (t - NK)];
    else if (t < NK + KHW + NC) ch[t - NK - KHW] = g_chan[b * NC + (t - NK - KHW)];
    else if (t == NK + KHW + NC) fo = g_filt[b * NO + o];
    __syncthreads();

    const float* wo = weight + (size_t)o * (NC * KHW);
    const int cp  = t / KHW;         // 0..31  (half2 pair index over all 64 c)
    const int khw = t - cp * KHW;    // 0..8
    const int c0  = 2 * cp;
    float a0 = 0.f, a1 = 0.f;
    #pragma unroll
    for (int k = 0; k < NK; k++) {
        const float* wk = wo + (size_t)k * NO * NC * KHW;
        a0 += ka[k] * wk[c0 * KHW + khw];
        a1 += ka[k] * wk[(c0 + 1) * KHW + khw];
    }
    const float g = fo * sp[khw];
    const __half2 hv = __floats2half2_rn(a0 * g * ch[c0], a1 * g * ch[c0 + 1]);
    const int chunk = cp >> 3;       // 16-channel chunk
    const int w     = cp & 7;        // half2 word within chunk
    const int kq    = w >> 2;        // k-half (8 channels)
    const int wi    = w & 3;         // word within 16B unit
    g_Wh[(((((size_t)b * NCH + chunk) * KHW + khw) * 2 + kq) * NO + o) * 4 + wi] =
        *(const uint32_t*)&hv;
}

// ---------------------------------------------------------------------------
// 4) Conv: fp16 m16n8k16 implicit GEMM, cp.async double-buffered, LDSM,
//    packed smem, pipelined taps, SMEM-TRANSPOSED COALESCED EPILOGUE.
//    Block = (row h, batch b): M=160 px, N=64 o, K=576.
//    320 thr = 10 warps = 5 M x 2 N groups; warp tile 32x32.
// ---------------------------------------------------------------------------
__global__ __launch_bounds__(320, 2)
void conv_kernel(float* __restrict__ out) {
    extern __shared__ __align__(16) uint32_t dsm[];
    const uint32_t sbase = smem_u32(dsm);
    // layout: xs[2][3888] then ws[2][4608] (u32 words); epilogue reuses dsm

    const int h    = blockIdx.x;
    const int b    = blockIdx.y;
    const int tid  = threadIdx.x;
    const int lane = tid & 31;
    const int warp = tid >> 5;
    const int mw   = (warp % 5) * 32;
    const int nw   = (warp / 5) * 32;
    const int l16  = lane & 15;
    const int lq   = lane >> 4;         // k-half
    const int lg   = lane >> 2;
    const int lk   = lane & 3;

    // zero the boundary columns (cols 0 and 161): 3 kh x 2 kq x 2 cols x 2 bufs
    if (tid < 96) {
        const int w    = tid & 3;
        const int u    = tid >> 2;           // 0..23
        const int col2 = u & 1;
        const int kq   = (u >> 1) & 1;
        const int kh   = (u >> 2) % 3;
        const int buf  = u / 12;
        dsm[buf * XS_WORDS_BUF + ((kh * 2 + kq) * 162 + col2 * 161) * 4 + w] = 0u;
    }

    float acc[2][4][4];
    #pragma unroll
    for (int i = 0; i < 2; i++)
        #pragma unroll
        for (int j = 0; j < 4; j++)
            #pragma unroll
            for (int k = 0; k < 4; k++) acc[i][j][k] = 0.f;

    // ---- async stage chunk ci into buffer buf ----
    auto issue_chunk = [&](int ci, int buf) {
        // x: 3 rows x 2 kq x 160 cols of 16B = 960 cp16
        #pragma unroll
        for (int it = 0; it < 3; it++) {
            const int e   = tid + it * 320;      // < 960
            const int q   = e & 1;
            const int c   = (e >> 1) % 160;
            const int kh  = e / 320;
            const int row = h - 1 + kh;
            const bool valid = (unsigned)row < NH;
            const uint32_t* src = g_xh + (((size_t)b * NH + (valid ? row : 0)) * NW + c) * 32
                                + ci * 8 + q * 4;
            const uint32_t dst = sbase + (buf * XS_WORDS_BUF
                                 + ((kh * 2 + q) * 162 + c + 1) * 4) * 4;
            cp16(dst, src, valid);
        }
        // weights: 4608 words = 1152 x 16B (raw copy of pre-packed image)
        const uint32_t* wsrc = g_Wh + ((size_t)b * NCH + ci) * WS_WORDS_BUF;
        #pragma unroll
        for (int it = 0; it < 4; it++) {
            const int e = tid + it * 320;
            if (e < 1152) {
                const uint32_t dst = sbase + (2 * XS_WORDS_BUF + buf * WS_WORDS_BUF + e * 4) * 4;
                cp16(dst, wsrc + e * 4, true);
            }
        }
        asm volatile("cp.async.commit_group;" ::: "memory");
    };

    issue_chunk(0, 0);

    for (int ci = 0; ci < NCH; ci++) {
        if (ci + 1 < NCH) {
            issue_chunk(ci + 1, (ci + 1) & 1);
            asm volatile("cp.async.wait_group 1;" ::: "memory");
        } else {
            asm volatile("cp.async.wait_group 0;" ::: "memory");
        }
        __syncthreads();

        const int buf = ci & 1;
        const uint32_t xsb = sbase + buf * XS_WORDS_BUF * 4;
        const uint32_t wsb = sbase + (2 * XS_WORDS_BUF + buf * WS_WORDS_BUF) * 4;

        // fragment loader for a given tap
        auto load_frags = [&](int tap, uint32_t af[2][4], uint32_t bf[4][2]) {
            const int kh = tap / 3;
            const int kw = tap - kh * 3;
            const uint32_t a0 = xsb + ((kh * 2 + lq) * 162 + mw + l16 + kw) * 16;
            ldsm_x4(af[0][0], af[0][1], af[0][2], af[0][3], a0);
            ldsm_x4(af[1][0], af[1][1], af[1][2], af[1][3], a0 + 16 * 16);
            const uint32_t b0 = wsb + ((tap * 2 + lq) * 64 + nw + l16) * 16;
            uint32_t r0, r1, r2, r3;
            ldsm_x4(r0, r1, r2, r3, b0);
            bf[0][0] = r0; bf[1][0] = r1; bf[0][1] = r2; bf[1][1] = r3;
            ldsm_x4(r0, r1, r2, r3, b0 + 16 * 16);
            bf[2][0] = r0; bf[3][0] = r1; bf[2][1] = r2; bf[3][1] = r3;
        };

        // software pipeline: fragments loaded one tap ahead (ping-pong regs)
        uint32_t afp[2][2][4], bfp[2][4][2];
        load_frags(0, afp[0], bfp[0]);
        #pragma unroll
        for (int tap = 0; tap < KHW; tap++) {
            const int cur = tap & 1;
            if (tap + 1 < KHW)
                load_frags(tap + 1, afp[cur ^ 1], bfp[cur ^ 1]);
            #pragma unroll
            for (int mt = 0; mt < 2; mt++)
                #pragma unroll
                for (int nt = 0; nt < 4; nt++)
                    mma16(acc[mt][nt], afp[cur][mt], bfp[cur][nt]);
        }
        __syncthreads();
    }

    // --- epilogue: smem transpose (pad 172: conflict-free stores, f4-aligned)
    float* so = (float*)dsm;
    #pragma unroll
    for (int mt = 0; mt < 2; mt++) {
        const int m = mw + mt * 16 + lg;
        #pragma unroll
        for (int nt = 0; nt < 4; nt++) {
            const int o = nw + nt * 8 + 2 * lk;
            so[o * 172 + m]           = acc[mt][nt][0];
            so[(o + 1) * 172 + m]     = acc[mt][nt][1];
            so[o * 172 + m + 8]       = acc[mt][nt][2];
            so[(o + 1) * 172 + m + 8] = acc[mt][nt][3];
        }
    }
    __syncthreads();

    // coalesced float4 stores: 64 o-rows x 40 float4
    {
        const int oo = tid / 40;        // 0..7
        const int j  = tid - oo * 40;   // 0..39
        float* obase = out + (size_t)b * NO * PLANE + (size_t)h * NW + j * 4;
        #pragma unroll
        for (int it = 0; it < 8; it++) {
            const int o = oo + it * 8;
            const float4 v = *(const float4*)&so[o * 172 + j * 4];
            *(float4*)(obase + (size_t)o * PLANE) = v;
        }
    }
}

// ---------------------------------------------------------------------------
extern "C" void kernel_launch(void* const* d_in, const int* in_sizes, int n_in,
                              void* d_out, int out_size) {
    const float* x      = (const float*)d_in[0];
    const float* scale  = (const float*)d_in[1];
    const float* rw1    = (const float*)d_in[2];
    const float* rb1    = (const float*)d_in[3];
    const float* rw2    = (const float*)d_in[4];
    const float* rb2    = (const float*)d_in[5];
    const float* fc_w   = (const float*)d_in[6];
    const float* bn_g   = (const float*)d_in[7];
    const float* bn_b   = (const float*)d_in[8];
    const float* bn_m   = (const float*)d_in[9];
    const float* bn_v   = (const float*)d_in[10];
    const float* cfc_w  = (const float*)d_in[11];
    const float* cfc_b  = (const float*)d_in[12];
    const float* ffc_w  = (const float*)d_in[13];
    const float* ffc_b  = (const float*)d_in[14];
    const float* sfc_w  = (const float*)d_in[15];
    const float* sfc_b  = (const float*)d_in[16];
    const float* kfc_w  = (const float*)d_in[17];
    const float* kfc_b  = (const float*)d_in[18];
    const float* weight = (const float*)d_in[19];
    float* out = (float*)d_out;

    cudaFuncSetAttribute(conv_kernel, cudaFuncAttributeMaxDynamicSharedMemorySize,
                         SMEM_BYTES);

    dim3 pgrid(NH, NB);
    xprep_kernel<<<pgrid, 640>>>(x);
    att_kernel<<<NB, 128>>>(scale, rw1, rb1, rw2, rb2, fc_w,
                            bn_g, bn_b, bn_m, bn_v,
                            cfc_w, cfc_b, ffc_w, ffc_b,
                            sfc_w, sfc_b, kfc_w, kfc_b);
    wprep_kernel<<<NB * NO, 288>>>(weight);
    dim3 grid(NH, NB);
    conv_kernel<<<grid, 320, SMEM_BYTES>>>(out);
}

// round 16
// speedup vs baseline: 1.0476x; 1.0476x over previous
#include <cuda_runtime.h>
#include <cuda_fp16.h>
#include <cstdint>
#include <math.h>

// Problem constants
#define NB 16
#define NC 64
#define NO 64
#define NH 160
#define NW 160
#define NK 8
#define NA 16
#define KHW 9
#define PLANE (NH*NW)          // 25600
#define NCH 4                  // channel chunks of 16
// Packed 16B-unit smem layouts (no padding, conflict-free by unit addressing)
#define XS_WORDS_BUF (3*2*162*4)   // 3888 u32: [kh][kq][col] units
#define WS_WORDS_BUF (KHW*2*NO*4)  // 4608 u32: [tap][kq][o] units
#define SMEM_BYTES ((2*XS_WORDS_BUF + 2*WS_WORDS_BUF) * 4)   // 67968

// Scratch (device globals; no allocation allowed)
__device__ float    g_rows[NB*NH*NC];          // per-(b,row) channel sums
__device__ float    g_chan[NB*NC];
__device__ float    g_filt[NB*NO];
__device__ float    g_spat[NB*KHW];
__device__ float    g_katt[NB*NK];
__device__ uint32_t g_Wh  [NB*NCH*WS_WORDS_BUF];        // pre-packed B image
__device__ uint32_t g_xh  [(size_t)NB*NH*NW*32];        // x as half2, channel-last

// ---------------------------------------------------------------------------
__device__ __forceinline__ uint32_t smem_u32(const void* p) {
    uint32_t a;
    asm("{ .reg .u64 t; cvta.to.shared.u64 t, %1; cvt.u32.u64 %0, t; }" : "=r"(a) : "l"(p));
    return a;
}
__device__ __forceinline__ void mma16(float* d, const uint32_t* a, const uint32_t* b) {
    asm volatile(
        "mma.sync.aligned.m16n8k16.row.col.f32.f16.f16.f32 "
        "{%0,%1,%2,%3}, {%4,%5,%6,%7}, {%8,%9}, {%0,%1,%2,%3};"
        : "+f"(d[0]), "+f"(d[1]), "+f"(d[2]), "+f"(d[3])
        : "r"(a[0]), "r"(a[1]), "r"(a[2]), "r"(a[3]), "r"(b[0]), "r"(b[1]));
}
__device__ __forceinline__ void ldsm_x4(uint32_t& r0, uint32_t& r1, uint32_t& r2,
                                        uint32_t& r3, uint32_t addr) {
    asm volatile("ldmatrix.sync.aligned.m8n8.x4.shared.b16 {%0,%1,%2,%3}, [%4];"
                 : "=r"(r0), "=r"(r1), "=r"(r2), "=r"(r3) : "r"(addr));
}
__device__ __forceinline__ void cp16(uint32_t dst, const void* src, bool valid) {
    const int sz = valid ? 16 : 0;
    asm volatile("cp.async.cg.shared.global [%0], [%1], 16, %2;"
                 :: "r"(dst), "l"(src), "r"(sz) : "memory");
}

// ---------------------------------------------------------------------------
// 1) xprep: x [b][c][h][w] fp32 -> g_xh [b][h][w][cp] half2 (channel-last),
//    coalesced writes, per-(b,row) channel sums. 640 threads, div/mod hoisted.
// ---------------------------------------------------------------------------
__global__ __launch_bounds__(640)
void xprep_kernel(const float* __restrict__ x) {
    __shared__ float s[NW * 66];           // 42240 B
    const int row = blockIdx.x;
    const int b   = blockIdx.y;
    const int tid = threadIdx.x;
    const int cb  = tid / NW;              // 0..3
    const int col = tid - cb * NW;         // 0..159

    const float* xr = x + ((size_t)b * NC * NH + row) * NW;
    #pragma unroll
    for (int it = 0; it < 16; it++) {
        const int c = cb + it * 4;
        s[col * 66 + c] = xr[(size_t)c * PLANE + col];
    }
    __syncthreads();

    if (tid < NC) {
        float a = 0.f;
        #pragma unroll 8
        for (int px = 0; px < NW; px++) a += s[px * 66 + tid];
        g_rows[((size_t)b * NH + row) * NC + tid] = a;
    }

    uint32_t* dstrow = g_xh + (((size_t)b * NH + row) * NW) * 32;
    #pragma unroll
    for (int it = 0; it < 8; it++) {
        const int e  = tid + it * 640;     // < 5120
        const int px = e >> 5;
        const int w  = e & 31;
        const float2 v = *(const float2*)&s[px * 66 + 2 * w];
        const __half2 hv = __floats2half2_rn(v.x, v.y);
        dstrow[e] = *(const uint32_t*)&hv;
    }
}

// ---------------------------------------------------------------------------
// 2) Routing MLP + BN + 4 attention heads: one block (128 thr) per batch b.
// ---------------------------------------------------------------------------
__global__ void att_kernel(const float* __restrict__ scale,
                           const float* __restrict__ rw1, const float* __restrict__ rb1,
                           const float* __restrict__ rw2, const float* __restrict__ rb2,
                           const float* __restrict__ fc_w,
                           const float* __restrict__ bn_g, const float* __restrict__ bn_b,
                           const float* __restrict__ bn_m, const float* __restrict__ bn_v,
                           const float* __restrict__ cfc_w, const float* __restrict__ cfc_b,
                           const float* __restrict__ ffc_w, const float* __restrict__ ffc_b,
                           const float* __restrict__ sfc_w, const float* __restrict__ sfc_b,
                           const float* __restrict__ kfc_w, const float* __restrict__ kfc_b) {
    const int b = blockIdx.x;
    const int t = threadIdx.x;
    __shared__ float p[2][64], s[66], h1[128], rt[64], v[16], kl[8];

    {   // GAP: 2 threads per channel, 80 rows each, fixed-order combine
        const int c    = t & 63;
        const int half = t >> 6;
        float a = 0.f;
        #pragma unroll 8
        for (int r = half * 80; r < half * 80 + 80; r++)
            a += g_rows[((size_t)b * NH + r) * NC + c];
        p[half][c] = a;
    }
    __syncthreads();
    if (t < 2) s[t] = 1.f / scale[t];
    if (t >= 2 && t < 66)
        s[t] = (p[0][t - 2] + p[1][t - 2]) * (1.f / (float)PLANE);
    __syncthreads();
    {   // layer 1: [128,66]
        float a = rb1[t];
        #pragma unroll 6
        for (int i = 0; i < 66; i++) a += rw1[t * 66 + i] * s[i];
        h1[t] = fmaxf(a, 0.f);
    }
    __syncthreads();
    if (t < 64) {   // layer 2: [64,128]
        float a = rb2[t];
        #pragma unroll 8
        for (int i = 0; i < 128; i++) a += rw2[t * 128 + i] * h1[i];
        rt[t] = fmaxf(a, 0.f);
    }
    __syncthreads();
    if (t < NA) {   // trunk: fc (no bias) + BN(eval) + relu
        float a = 0.f;
        #pragma unroll 8
        for (int i = 0; i < 64; i++) a += fc_w[t * 64 + i] * rt[i];
        a = (a - bn_m[t]) * rsqrtf(bn_v[t] + 1e-5f) * bn_g[t] + bn_b[t];
        v[t] = fmaxf(a, 0.f);
    }
    __syncthreads();
    if (t < 64) {
        float a = cfc_b[t], f = ffc_b[t];
        #pragma unroll
        for (int i = 0; i < NA; i++) { a += cfc_w[t * NA + i] * v[i]; f += ffc_w[t * NA + i] * v[i]; }
        g_chan[b * NC + t] = 1.f / (1.f + expf(-a));
        g_filt[b * NO + t] = 1.f / (1.f + expf(-f));
    }
    if (t < KHW) {
        float a = sfc_b[t];
        #pragma unroll
        for (int i = 0; i < NA; i++) a += sfc_w[t * NA + i] * v[i];
        g_spat[b * KHW + t] = 1.f / (1.f + expf(-a));
    }
    if (t < NK) {
        float a = kfc_b[t];
        #pragma unroll
        for (int i = 0; i < NA; i++) a += kfc_w[t * NA + i] * v[i];
        kl[t] = a;
    }
    __syncthreads();
    if (t == 0) {   // softmax over 8 experts
        float m = kl[0];
        #pragma unroll
        for (int i = 1; i < NK; i++) m = fmaxf(m, kl[i]);
        float e[NK], sum = 0.f;
        #pragma unroll
        for (int i = 0; i < NK; i++) { e[i] = expf(kl[i] - m); sum += e[i]; }
        float inv = 1.f / sum;
        #pragma unroll
        for (int i = 0; i < NK; i++) g_katt[b * NK + i] = e[i] * inv;
    }
}

// ---------------------------------------------------------------------------
// 3) Aggregated+gated weights -> packed B image, COALESCED reads.
//    Threads walk e = c*9+khw linearly (consecutive fp32 across the warp for
//    each of the 8 expert tensors), then store single fp16 halves into the
//    packed [b][chunk][tap][kq][o] unit layout (same bits as before).
// ---------------------------------------------------------------------------
__global__ __launch_bounds__(288)
void wprep_kernel(const float* __restrict__ weight) {
    const int b = blockIdx.x >> 6;
    const int o = blockIdx.x & 63;
    __shared__ float ka[NK], sp[KHW], ch[NC], fo;
    const int t = threadIdx.x;
    if (t < NK)                 ka[t]      = g_katt[b * NK + t];
    else if (t < NK + KHW)      sp[t - NK] = g_spat[b * KHW + (t - NK)];
    else if (t < NK + KHW + NC) ch[t - NK - KHW] = g_chan[b * NC + (t - NK - KHW)];
    else if (t == NK + KHW + NC) fo = g_filt[b * NO + o];
    __syncthreads();

    const float* wo = weight + (size_t)o * (NC * KHW);
    uint16_t* wh16 = (uint16_t*)g_Wh;
    #pragma unroll
    for (int it = 0; it < 2; it++) {
        const int e   = t + it * 288;        // 0..575, coalesced
        const int c   = e / KHW;
        const int khw = e - c * KHW;
        float a = 0.f;
        #pragma unroll
        for (int k = 0; k < NK; k++)
            a += ka[k] * wo[(size_t)k * NO * NC * KHW + e];
        const float val = a * fo * ch[c] * sp[khw];
        const __half hv = __float2half_rn(val);
        // packed image position (identical to previous layout)
        const int chunk = c >> 4;
        const int cc    = c & 15;
        const int kq    = cc >> 3;
        const int wi    = (c >> 1) & 3;
        const int hpos  = c & 1;
        const size_t idx16 =
            (((((size_t)b * NCH + chunk) * KHW + khw) * 2 + kq) * NO + o) * 8
            + wi * 2 + hpos;
        wh16[idx16] = *(const uint16_t*)&hv;
    }
}

// ---------------------------------------------------------------------------
// 4) Conv: fp16 m16n8k16 implicit GEMM, cp.async double-buffered, LDSM,
//    packed smem (66 KB/CTA -> 3 CTAs/SM).  (R13-proven best)
//    Block = (row h, batch b): M=160 px, N=64 o, K=576.
//    320 thr = 10 warps = 5 M x 2 N groups; warp tile 32x32.
// ---------------------------------------------------------------------------
__global__ __launch_bounds__(320, 3)
void conv_kernel(float* __restrict__ out) {
    extern __shared__ __align__(16) uint32_t dsm[];
    const uint32_t sbase = smem_u32(dsm);
    // layout: xs[2][3888] then ws[2][4608] (u32 words)

    const int h    = blockIdx.x;
    const int b    = blockIdx.y;
    const int tid  = threadIdx.x;
    const int lane = tid & 31;
    const int warp = tid >> 5;
    const int mw   = (warp % 5) * 32;
    const int nw   = (warp / 5) * 32;
    const int l16  = lane & 15;
    const int lq   = lane >> 4;         // k-half
    const int lg   = lane >> 2;
    const int lk   = lane & 3;

    // zero the boundary columns (cols 0 and 161): 3 kh x 2 kq x 2 cols x 2 bufs
    if (tid < 96) {
        const int w    = tid & 3;
        const int u    = tid >> 2;           // 0..23
        const int col2 = u & 1;
        const int kq   = (u >> 1) & 1;
        const int kh   = (u >> 2) % 3;
        const int buf  = u / 12;
        dsm[buf * XS_WORDS_BUF + ((kh * 2 + kq) * 162 + col2 * 161) * 4 + w] = 0u;
    }

    float acc[2][4][4];
    #pragma unroll
    for (int i = 0; i < 2; i++)
        #pragma unroll
        for (int j = 0; j < 4; j++)
            #pragma unroll
            for (int k = 0; k < 4; k++) acc[i][j][k] = 0.f;

    // ---- async stage chunk ci into buffer buf ----
    auto issue_chunk = [&](int ci, int buf) {
        // x: 3 rows x 2 kq x 160 cols of 16B = 960 cp16
        #pragma unroll
        for (int it = 0; it < 3; it++) {
            const int e   = tid + it * 320;      // < 960
            const int q   = e & 1;
            const int c   = (e >> 1) % 160;
            const int kh  = e / 320;
            const int row = h - 1 + kh;
            const bool valid = (unsigned)row < NH;
            const uint32_t* src = g_xh + (((size_t)b * NH + (valid ? row : 0)) * NW + c) * 32
                                + ci * 8 + q * 4;
            const uint32_t dst = sbase + (buf * XS_WORDS_BUF
                                 + ((kh * 2 + q) * 162 + c + 1) * 4) * 4;
            cp16(dst, src, valid);
        }
        // weights: 4608 words = 1152 x 16B (raw copy of pre-packed image)
        const uint32_t* wsrc = g_Wh + ((size_t)b * NCH + ci) * WS_WORDS_BUF;
        #pragma unroll
        for (int it = 0; it < 4; it++) {
            const int e = tid + it * 320;
            if (e < 1152) {
                const uint32_t dst = sbase + (2 * XS_WORDS_BUF + buf * WS_WORDS_BUF + e * 4) * 4;
                cp16(dst, wsrc + e * 4, true);
            }
        }
        asm volatile("cp.async.commit_group;" ::: "memory");
    };

    issue_chunk(0, 0);

    for (int ci = 0; ci < NCH; ci++) {
        if (ci + 1 < NCH) {
            issue_chunk(ci + 1, (ci + 1) & 1);
            asm volatile("cp.async.wait_group 1;" ::: "memory");
        } else {
            asm volatile("cp.async.wait_group 0;" ::: "memory");
        }
        __syncthreads();

        const int buf = ci & 1;
        const uint32_t xsb = sbase + buf * XS_WORDS_BUF * 4;
        const uint32_t wsb = sbase + (2 * XS_WORDS_BUF + buf * WS_WORDS_BUF) * 4;

        #pragma unroll
        for (int tap = 0; tap < KHW; tap++) {
            const int kh = tap / 3;
            const int kw = tap - kh * 3;

            uint32_t af[2][4], bf[4][2];
            // A fragments: 16B units [kh][kq][col]; lane -> col = mw+l16+kw
            const uint32_t a0 = xsb + ((kh * 2 + lq) * 162 + mw + l16 + kw) * 16;
            ldsm_x4(af[0][0], af[0][1], af[0][2], af[0][3], a0);
            ldsm_x4(af[1][0], af[1][1], af[1][2], af[1][3], a0 + 16 * 16);
            // B fragments: 16B units [tap][kq][o]; lane -> o = nw+l16
            const uint32_t b0 = wsb + ((tap * 2 + lq) * 64 + nw + l16) * 16;
            uint32_t r0, r1, r2, r3;
            ldsm_x4(r0, r1, r2, r3, b0);
            bf[0][0] = r0; bf[1][0] = r1; bf[0][1] = r2; bf[1][1] = r3;
            ldsm_x4(r0, r1, r2, r3, b0 + 16 * 16);
            bf[2][0] = r0; bf[3][0] = r1; bf[2][1] = r2; bf[3][1] = r3;

            #pragma unroll
            for (int mt = 0; mt < 2; mt++)
                #pragma unroll
                for (int nt = 0; nt < 4; nt++)
                    mma16(acc[mt][nt], af[mt], bf[nt]);
        }
        __syncthreads();
    }

    // --- epilogue: d0:(m,n) d1:(m,n+1) d2:(m+8,n) d3:(m+8,n+1) ---
    #pragma unroll
    for (int mt = 0; mt < 2; mt++) {
        const int m = mw + mt * 16 + lg;
        #pragma unroll
        for (int nt = 0; nt < 4; nt++) {
            const int o = nw + nt * 8 + 2 * lk;
            float* ob = out + ((size_t)b * NO + o) * PLANE + (size_t)h * NW;
            ob[m]             = acc[mt][nt][0];
            ob[PLANE + m]     = acc[mt][nt][1];
            ob[m + 8]         = acc[mt][nt][2];
            ob[PLANE + m + 8] = acc[mt][nt][3];
        }
    }
}

// ---------------------------------------------------------------------------
extern "C" void kernel_launch(void* const* d_in, const int* in_sizes, int n_in,
                              void* d_out, int out_size) {
    const float* x      = (const float*)d_in[0];
    const float* scale  = (const float*)d_in[1];
    const float* rw1    = (const float*)d_in[2];
    const float* rb1    = (const float*)d_in[3];
    const float* rw2    = (const float*)d_in[4];
    const float* rb2    = (const float*)d_in[5];
    const float* fc_w   = (const float*)d_in[6];
    const float* bn_g   = (const float*)d_in[7];
    const float* bn_b   = (const float*)d_in[8];
    const float* bn_m   = (const float*)d_in[9];
    const float* bn_v   = (const float*)d_in[10];
    const float* cfc_w  = (const float*)d_in[11];
    const float* cfc_b  = (const float*)d_in[12];
    const float* ffc_w  = (const float*)d_in[13];
    const float* ffc_b  = (const float*)d_in[14];
    const float* sfc_w  = (const float*)d_in[15];
    const float* sfc_b  = (const float*)d_in[16];
    const float* kfc_w  = (const float*)d_in[17];
    const float* kfc_b  = (const float*)d_in[18];
    const float* weight = (const float*)d_in[19];
    float* out = (float*)d_out;

    cudaFuncSetAttribute(conv_kernel, cudaFuncAttributeMaxDynamicSharedMemorySize,
                         SMEM_BYTES);

    dim3 pgrid(NH, NB);
    xprep_kernel<<<pgrid, 640>>>(x);
    att_kernel<<<NB, 128>>>(scale, rw1, rb1, rw2, rb2, fc_w,
                            bn_g, bn_b, bn_m, bn_v,
                            cfc_w, cfc_b, ffc_w, ffc_b,
                            sfc_w, sfc_b, kfc_w, kfc_b);
    wprep_kernel<<<NB * NO, 288>>>(weight);
    dim3 grid(NH, NB);
    conv_kernel<<<grid, 320, SMEM_BYTES>>>(out);
}

// round 17
// speedup vs baseline: 1.0496x; 1.0019x over previous
#include <cuda_runtime.h>
#include <cuda_fp16.h>
#include <cstdint>
#include <math.h>

// Problem constants
#define NB 16
#define NC 64
#define NO 64
#define NH 160
#define NW 160
#define NK 8
#define NA 16
#define KHW 9
#define PLANE (NH*NW)          // 25600
#define NCH 4                  // channel chunks of 16
// Packed 16B-unit smem layouts (no padding, conflict-free by unit addressing)
#define XS_WORDS_BUF (3*2*162*4)   // 3888 u32: [kh][kq][col] units
#define WS_WORDS_BUF (KHW*2*NO*4)  // 4608 u32: [tap][kq][o] units
#define SMEM_BYTES ((2*XS_WORDS_BUF + 2*WS_WORDS_BUF) * 4)   // 67968

// Scratch (device globals; no allocation allowed)
__device__ float    g_rows[NB*NH*NC];          // per-(b,row) channel sums
__device__ float    g_chan[NB*NC];
__device__ float    g_filt[NB*NO];
__device__ float    g_spat[NB*KHW];
__device__ float    g_katt[NB*NK];
__device__ uint32_t g_Wh  [NB*NCH*WS_WORDS_BUF];        // pre-packed B image
__device__ uint32_t g_xh  [(size_t)NB*NH*NW*32];        // x as half2, channel-last

// ---------------------------------------------------------------------------
__device__ __forceinline__ uint32_t smem_u32(const void* p) {
    uint32_t a;
    asm("{ .reg .u64 t; cvta.to.shared.u64 t, %1; cvt.u32.u64 %0, t; }" : "=r"(a) : "l"(p));
    return a;
}
__device__ __forceinline__ void mma16(float* d, const uint32_t* a, const uint32_t* b) {
    asm volatile(
        "mma.sync.aligned.m16n8k16.row.col.f32.f16.f16.f32 "
        "{%0,%1,%2,%3}, {%4,%5,%6,%7}, {%8,%9}, {%0,%1,%2,%3};"
        : "+f"(d[0]), "+f"(d[1]), "+f"(d[2]), "+f"(d[3])
        : "r"(a[0]), "r"(a[1]), "r"(a[2]), "r"(a[3]), "r"(b[0]), "r"(b[1]));
}
__device__ __forceinline__ void ldsm_x4(uint32_t& r0, uint32_t& r1, uint32_t& r2,
                                        uint32_t& r3, uint32_t addr) {
    asm volatile("ldmatrix.sync.aligned.m8n8.x4.shared.b16 {%0,%1,%2,%3}, [%4];"
                 : "=r"(r0), "=r"(r1), "=r"(r2), "=r"(r3) : "r"(addr));
}
__device__ __forceinline__ void cp16(uint32_t dst, const void* src, bool valid) {
    const int sz = valid ? 16 : 0;
    asm volatile("cp.async.cg.shared.global [%0], [%1], 16, %2;"
                 :: "r"(dst), "l"(src), "r"(sz) : "memory");
}

// ---------------------------------------------------------------------------
// 1) xprep: x [b][c][h][w] fp32 -> g_xh [b][h][w][cp] half2 (channel-last),
//    coalesced writes, per-(b,row) channel sums. 640 threads, div/mod hoisted.
// ---------------------------------------------------------------------------
__global__ __launch_bounds__(640)
void xprep_kernel(const float* __restrict__ x) {
    __shared__ float s[NW * 66];           // 42240 B
    const int row = blockIdx.x;
    const int b   = blockIdx.y;
    const int tid = threadIdx.x;
    const int cb  = tid / NW;              // 0..3
    const int col = tid - cb * NW;         // 0..159

    const float* xr = x + ((size_t)b * NC * NH + row) * NW;
    #pragma unroll
    for (int it = 0; it < 16; it++) {
        const int c = cb + it * 4;
        s[col * 66 + c] = xr[(size_t)c * PLANE + col];
    }
    __syncthreads();

    if (tid < NC) {
        float a = 0.f;
        #pragma unroll 8
        for (int px = 0; px < NW; px++) a += s[px * 66 + tid];
        g_rows[((size_t)b * NH + row) * NC + tid] = a;
    }

    uint32_t* dstrow = g_xh + (((size_t)b * NH + row) * NW) * 32;
    #pragma unroll
    for (int it = 0; it < 8; it++) {
        const int e  = tid + it * 640;     // < 5120
        const int px = e >> 5;
        const int w  = e & 31;
        const float2 v = *(const float2*)&s[px * 66 + 2 * w];
        const __half2 hv = __floats2half2_rn(v.x, v.y);
        dstrow[e] = *(const uint32_t*)&hv;
    }
}

// ---------------------------------------------------------------------------
// 2) Routing MLP + BN + 4 attention heads: one block (128 thr) per batch b.
// ---------------------------------------------------------------------------
__global__ void att_kernel(const float* __restrict__ scale,
                           const float* __restrict__ rw1, const float* __restrict__ rb1,
                           const float* __restrict__ rw2, const float* __restrict__ rb2,
                           const float* __restrict__ fc_w,
                           const float* __restrict__ bn_g, const float* __restrict__ bn_b,
                           const float* __restrict__ bn_m, const float* __restrict__ bn_v,
                           const float* __restrict__ cfc_w, const float* __restrict__ cfc_b,
                           const float* __restrict__ ffc_w, const float* __restrict__ ffc_b,
                           const float* __restrict__ sfc_w, const float* __restrict__ sfc_b,
                           const float* __restrict__ kfc_w, const float* __restrict__ kfc_b) {
    const int b = blockIdx.x;
    const int t = threadIdx.x;
    __shared__ float p[2][64], s[66], h1[128], rt[64], v[16], kl[8];

    {   // GAP: 2 threads per channel, 80 rows each, fixed-order combine
        const int c    = t & 63;
        const int half = t >> 6;
        float a = 0.f;
        #pragma unroll 8
        for (int r = half * 80; r < half * 80 + 80; r++)
            a += g_rows[((size_t)b * NH + r) * NC + c];
        p[half][c] = a;
    }
    __syncthreads();
    if (t < 2) s[t] = 1.f / scale[t];
    if (t >= 2 && t < 66)
        s[t] = (p[0][t - 2] + p[1][t - 2]) * (1.f / (float)PLANE);
    __syncthreads();
    {   // layer 1: [128,66]
        float a = rb1[t];
        #pragma unroll 6
        for (int i = 0; i < 66; i++) a += rw1[t * 66 + i] * s[i];
        h1[t] = fmaxf(a, 0.f);
    }
    __syncthreads();
    if (t < 64) {   // layer 2: [64,128]
        float a = rb2[t];
        #pragma unroll 8
        for (int i = 0; i < 128; i++) a += rw2[t * 128 + i] * h1[i];
        rt[t] = fmaxf(a, 0.f);
    }
    __syncthreads();
    if (t < NA) {   // trunk: fc (no bias) + BN(eval) + relu
        float a = 0.f;
        #pragma unroll 8
        for (int i = 0; i < 64; i++) a += fc_w[t * 64 + i] * rt[i];
        a = (a - bn_m[t]) * rsqrtf(bn_v[t] + 1e-5f) * bn_g[t] + bn_b[t];
        v[t] = fmaxf(a, 0.f);
    }
    __syncthreads();
    if (t < 64) {
        float a = cfc_b[t], f = ffc_b[t];
        #pragma unroll
        for (int i = 0; i < NA; i++) { a += cfc_w[t * NA + i] * v[i]; f += ffc_w[t * NA + i] * v[i]; }
        g_chan[b * NC + t] = 1.f / (1.f + expf(-a));
        g_filt[b * NO + t] = 1.f / (1.f + expf(-f));
    }
    if (t < KHW) {
        float a = sfc_b[t];
        #pragma unroll
        for (int i = 0; i < NA; i++) a += sfc_w[t * NA + i] * v[i];
        g_spat[b * KHW + t] = 1.f / (1.f + expf(-a));
    }
    if (t < NK) {
        float a = kfc_b[t];
        #pragma unroll
        for (int i = 0; i < NA; i++) a += kfc_w[t * NA + i] * v[i];
        kl[t] = a;
    }
    __syncthreads();
    if (t == 0) {   // softmax over 8 experts
        float m = kl[0];
        #pragma unroll
        for (int i = 1; i < NK; i++) m = fmaxf(m, kl[i]);
        float e[NK], sum = 0.f;
        #pragma unroll
        for (int i = 0; i < NK; i++) { e[i] = expf(kl[i] - m); sum += e[i]; }
        float inv = 1.f / sum;
        #pragma unroll
        for (int i = 0; i < NK; i++) g_katt[b * NK + i] = e[i] * inv;
    }
}

// ---------------------------------------------------------------------------
// 3) Aggregated+gated weights -> packed B image, COALESCED reads.
//    Threads walk e = c*9+khw linearly (consecutive fp32 across the warp for
//    each of the 8 expert tensors), then store single fp16 halves into the
//    packed [b][chunk][tap][kq][o] unit layout (same bits as before).
// ---------------------------------------------------------------------------
__global__ __launch_bounds__(288)
void wprep_kernel(const float* __restrict__ weight) {
    const int b = blockIdx.x >> 6;
    const int o = blockIdx.x & 63;
    __shared__ float ka[NK], sp[KHW], ch[NC], fo;
    const int t = threadIdx.x;
    if (t < NK)                 ka[t]      = g_katt[b * NK + t];
    else if (t < NK + KHW)      sp[t - NK] = g_spat[b * KHW + (t - NK)];
    else if (t < NK + KHW + NC) ch[t - NK - KHW] = g_chan[b * NC + (t - NK - KHW)];
    else if (t == NK + KHW + NC) fo = g_filt[b * NO + o];
    __syncthreads();

    const float* wo = weight + (size_t)o * (NC * KHW);
    uint16_t* wh16 = (uint16_t*)g_Wh;
    #pragma unroll
    for (int it = 0; it < 2; it++) {
        const int e   = t + it * 288;        // 0..575, coalesced
        const int c   = e / KHW;
        const int khw = e - c * KHW;
        float a = 0.f;
        #pragma unroll
        for (int k = 0; k < NK; k++)
            a += ka[k] * wo[(size_t)k * NO * NC * KHW + e];
        const float val = a * fo * ch[c] * sp[khw];
        const __half hv = __float2half_rn(val);
        // packed image position (identical to previous layout)
        const int chunk = c >> 4;
        const int cc    = c & 15;
        const int kq    = cc >> 3;
        const int wi    = (c >> 1) & 3;
        const int hpos  = c & 1;
        const size_t idx16 =
            (((((size_t)b * NCH + chunk) * KHW + khw) * 2 + kq) * NO + o) * 8
            + wi * 2 + hpos;
        wh16[idx16] = *(const uint16_t*)&hv;
    }
}

// ---------------------------------------------------------------------------
// 4) Conv: fp16 m16n8k16 implicit GEMM, cp.async double-buffered, LDSM,
//    packed smem (66 KB/CTA -> 3 CTAs/SM).  (R13-proven best)
//    Block = (row h, batch b): M=160 px, N=64 o, K=576.
//    320 thr = 10 warps = 5 M x 2 N groups; warp tile 32x32.
// ---------------------------------------------------------------------------
__global__ __launch_bounds__(320, 3)
void conv_kernel(float* __restrict__ out) {
    extern __shared__ __align__(16) uint32_t dsm[];
    const uint32_t sbase = smem_u32(dsm);
    // layout: xs[2][3888] then ws[2][4608] (u32 words)

    const int h    = blockIdx.x;
    const int b    = blockIdx.y;
    const int tid  = threadIdx.x;
    const int lane = tid & 31;
    const int warp = tid >> 5;
    const int mw   = (warp % 5) * 32;
    const int nw   = (warp / 5) * 32;
    const int l16  = lane & 15;
    const int lq   = lane >> 4;         // k-half
    const int lg   = lane >> 2;
    const int lk   = lane & 3;

    // zero the boundary columns (cols 0 and 161): 3 kh x 2 kq x 2 cols x 2 bufs
    if (tid < 96) {
        const int w    = tid & 3;
        const int u    = tid >> 2;           // 0..23
        const int col2 = u & 1;
        const int kq   = (u >> 1) & 1;
        const int kh   = (u >> 2) % 3;
        const int buf  = u / 12;
        dsm[buf * XS_WORDS_BUF + ((kh * 2 + kq) * 162 + col2 * 161) * 4 + w] = 0u;
    }

    float acc[2][4][4];
    #pragma unroll
    for (int i = 0; i < 2; i++)
        #pragma unroll
        for (int j = 0; j < 4; j++)
            #pragma unroll
            for (int k = 0; k < 4; k++) acc[i][j][k] = 0.f;

    // ---- async stage chunk ci into buffer buf ----
    auto issue_chunk = [&](int ci, int buf) {
        // x: 3 rows x 2 kq x 160 cols of 16B = 960 cp16
        #pragma unroll
        for (int it = 0; it < 3; it++) {
            const int e   = tid + it * 320;      // < 960
            const int q   = e & 1;
            const int c   = (e >> 1) % 160;
            const int kh  = e / 320;
            const int row = h - 1 + kh;
            const bool valid = (unsigned)row < NH;
            const uint32_t* src = g_xh + (((size_t)b * NH + (valid ? row : 0)) * NW + c) * 32
                                + ci * 8 + q * 4;
            const uint32_t dst = sbase + (buf * XS_WORDS_BUF
                                 + ((kh * 2 + q) * 162 + c + 1) * 4) * 4;
            cp16(dst, src, valid);
        }
        // weights: 4608 words = 1152 x 16B (raw copy of pre-packed image)
        const uint32_t* wsrc = g_Wh + ((size_t)b * NCH + ci) * WS_WORDS_BUF;
        #pragma unroll
        for (int it = 0; it < 4; it++) {
            const int e = tid + it * 320;
            if (e < 1152) {
                const uint32_t dst = sbase + (2 * XS_WORDS_BUF + buf * WS_WORDS_BUF + e * 4) * 4;
                cp16(dst, wsrc + e * 4, true);
            }
        }
        asm volatile("cp.async.commit_group;" ::: "memory");
    };

    issue_chunk(0, 0);

    for (int ci = 0; ci < NCH; ci++) {
        if (ci + 1 < NCH) {
            issue_chunk(ci + 1, (ci + 1) & 1);
            asm volatile("cp.async.wait_group 1;" ::: "memory");
        } else {
            asm volatile("cp.async.wait_group 0;" ::: "memory");
        }
        __syncthreads();

        const int buf = ci & 1;
        const uint32_t xsb = sbase + buf * XS_WORDS_BUF * 4;
        const uint32_t wsb = sbase + (2 * XS_WORDS_BUF + buf * WS_WORDS_BUF) * 4;

        #pragma unroll
        for (int tap = 0; tap < KHW; tap++) {
            const int kh = tap / 3;
            const int kw = tap - kh * 3;

            uint32_t af[2][4], bf[4][2];
            // A fragments: 16B units [kh][kq][col]; lane -> col = mw+l16+kw
            const uint32_t a0 = xsb + ((kh * 2 + lq) * 162 + mw + l16 + kw) * 16;
            ldsm_x4(af[0][0], af[0][1], af[0][2], af[0][3], a0);
            ldsm_x4(af[1][0], af[1][1], af[1][2], af[1][3], a0 + 16 * 16);
            // B fragments: 16B units [tap][kq][o]; lane -> o = nw+l16
            const uint32_t b0 = wsb + ((tap * 2 + lq) * 64 + nw + l16) * 16;
            uint32_t r0, r1, r2, r3;
            ldsm_x4(r0, r1, r2, r3, b0);
            bf[0][0] = r0; bf[1][0] = r1; bf[0][1] = r2; bf[1][1] = r3;
            ldsm_x4(r0, r1, r2, r3, b0 + 16 * 16);
            bf[2][0] = r0; bf[3][0] = r1; bf[2][1] = r2; bf[3][1] = r3;

            #pragma unroll
            for (int mt = 0; mt < 2; mt++)
                #pragma unroll
                for (int nt = 0; nt < 4; nt++)
                    mma16(acc[mt][nt], af[mt], bf[nt]);
        }
        __syncthreads();
    }

    // --- epilogue: d0:(m,n) d1:(m,n+1) d2:(m+8,n) d3:(m+8,n+1) ---
    #pragma unroll
    for (int mt = 0; mt < 2; mt++) {
        const int m = mw + mt * 16 + lg;
        #pragma unroll
        for (int nt = 0; nt < 4; nt++) {
            const int o = nw + nt * 8 + 2 * lk;
            float* ob = out + ((size_t)b * NO + o) * PLANE + (size_t)h * NW;
            ob[m]             = acc[mt][nt][0];
            ob[PLANE + m]     = acc[mt][nt][1];
            ob[m + 8]         = acc[mt][nt][2];
            ob[PLANE + m + 8] = acc[mt][nt][3];
        }
    }
}

// ---------------------------------------------------------------------------
extern "C" void kernel_launch(void* const* d_in, const int* in_sizes, int n_in,
                              void* d_out, int out_size) {
    const float* x      = (const float*)d_in[0];
    const float* scale  = (const float*)d_in[1];
    const float* rw1    = (const float*)d_in[2];
    const float* rb1    = (const float*)d_in[3];
    const float* rw2    = (const float*)d_in[4];
    const float* rb2    = (const float*)d_in[5];
    const float* fc_w   = (const float*)d_in[6];
    const float* bn_g   = (const float*)d_in[7];
    const float* bn_b   = (const float*)d_in[8];
    const float* bn_m   = (const float*)d_in[9];
    const float* bn_v   = (const float*)d_in[10];
    const float* cfc_w  = (const float*)d_in[11];
    const float* cfc_b  = (const float*)d_in[12];
    const float* ffc_w  = (const float*)d_in[13];
    const float* ffc_b  = (const float*)d_in[14];
    const float* sfc_w  = (const float*)d_in[15];
    const float* sfc_b  = (const float*)d_in[16];
    const float* kfc_w  = (const float*)d_in[17];
    const float* kfc_b  = (const float*)d_in[18];
    const float* weight = (const float*)d_in[19];
    float* out = (float*)d_out;

    cudaFuncSetAttribute(conv_kernel, cudaFuncAttributeMaxDynamicSharedMemorySize,
                         SMEM_BYTES);

    dim3 pgrid(NH, NB);
    xprep_kernel<<<pgrid, 640>>>(x);
    att_kernel<<<NB, 128>>>(scale, rw1, rb1, rw2, rb2, fc_w,
                            bn_g, bn_b, bn_m, bn_v,
                            cfc_w, cfc_b, ffc_w, ffc_b,
                            sfc_w, sfc_b, kfc_w, kfc_b);
    wprep_kernel<<<NB * NO, 288>>>(weight);
    dim3 grid(NH, NB);
    conv_kernel<<<grid, 320, SMEM_BYTES>>>(out);
}